// round 12
// baseline (speedup 1.0000x reference)
#include <cuda_runtime.h>
#include <cuda_fp16.h>
#include <cstdint>

#define B_   8
#define T_   16
#define H_   64
#define W_   64
#define CIN  32
#define F_   64
#define NC   256          // 4*F gates [i,f,c,o]
#define NSL  27           // 9 x-slices + 18 h-slices (K=32 each)

// Persistent state. h in fp16 (feeds fp16 MMA), c in fp32.
__device__ __half g_hh[2][B_ * H_ * W_ * F_];
__device__ float  g_c[B_ * H_ * W_ * F_];
// x pre-converted to fp16
__device__ __half g_xh[B_ * T_ * H_ * W_ * CIN];
// Weights pre-packed in MMA B-fragment order (verified R5/R7):
// [slice][warp_n][idx = kk*4+p][lane] -> uint4   (16 KB per slice)
__device__ uint4 g_bf[NSL][4][8][32];

#define XH_PITCH 80     // bytes per halo pixel row (x: 64B data + pad)
#define HH_PITCH 144    // bytes per halo pixel row (h: 128B data + pad)
#define SM_XH 0
#define SM_HH 8000                    // 100*80
#define SM_B  (8000 + 100 * 144)      // 22400
#define BSLICE 16384                  // one slice of B frags
#define SM_TOT (SM_B + 2 * BSLICE)    // 55168 B (dynamic)

__device__ __forceinline__ float hsig(float x) {
    return __saturatef((x + 3.0f) * 0.16666667f);  // hard_sigmoid
}
__device__ __forceinline__ uint32_t smem_u32(const void* p) {
    uint32_t a;
    asm("{ .reg .u64 t; cvta.to.shared.u64 t, %1; cvt.u32.u64 %0, t; }"
        : "=r"(a) : "l"(p));
    return a;
}
__device__ __forceinline__ uint64_t gaddr(const void* p) {
    uint64_t a;
    asm("cvta.to.global.u64 %0, %1;" : "=l"(a) : "l"(p));
    return a;
}

#define CP16(dst, src) \
    asm volatile("cp.async.ca.shared.global [%0], [%1], 16, 16;" \
                 :: "r"(dst), "l"(src) : "memory")
#define CP_COMMIT() asm volatile("cp.async.commit_group;" ::: "memory")
#define CP_WAIT1()  asm volatile("cp.async.wait_group 1;" ::: "memory")
#define CP_WAIT0()  asm volatile("cp.async.wait_group 0;" ::: "memory")

#define LDSV4(v, addr) \
    asm volatile("ld.shared.v4.u32 {%0,%1,%2,%3}, [%4];" \
        : "=r"((v).x), "=r"((v).y), "=r"((v).z), "=r"((v).w) : "r"(addr))

#define LDSM4(r0, r1, r2, r3, addr) \
    asm volatile("ldmatrix.sync.aligned.m8n8.x4.shared.b16 {%0,%1,%2,%3}, [%4];" \
        : "=r"(r0), "=r"(r1), "=r"(r2), "=r"(r3) : "r"(addr))

#define MMA16816(d, a0, a1, a2, a3, b0, b1) \
    asm volatile("mma.sync.aligned.m16n8k16.row.col.f32.f16.f16.f32 " \
        "{%0,%1,%2,%3}, {%4,%5,%6,%7}, {%8,%9}, {%0,%1,%2,%3};" \
        : "+f"((d)[0]), "+f"((d)[1]), "+f"((d)[2]), "+f"((d)[3]) \
        : "r"(a0), "r"(a1), "r"(a2), "r"(a3), "r"(b0), "r"(b1))

// ---- one-time preps ----
__global__ void prep_x(const float* __restrict__ x) {
    size_t i = ((size_t)blockIdx.x * 256 + threadIdx.x) * 4;
    float4 v = *(const float4*)(x + i);
    __half2 h2[2];
    h2[0] = __floats2half2_rn(v.x, v.y);
    h2[1] = __floats2half2_rn(v.z, v.w);
    *(uint2*)&g_xh[i] = *(uint2*)h2;
}

// Pack weights into B-fragment order (verified R5/R7).
__global__ void prep_bf(const float* __restrict__ Wt,
                        const float* __restrict__ Ut) {
    const int s    = blockIdx.x;          // 0..26
    const int wn   = blockIdx.y;          // 0..3
    const int idx  = threadIdx.x >> 5;    // 0..7
    const int lane = threadIdx.x & 31;
    const int kk = idx >> 2, p = idx & 3;

    uint32_t r[4];
    #pragma unroll
    for (int jm = 0; jm < 4; ++jm) {
        const int a  = 8 * jm + (lane >> 2);
        const int n  = wn * 64 + p * 16 + ((a >> 4) << 3) + (a & 7);
        const int jcol = ((n >> 4) & 3) * 64 + (n >> 6) * 16 + (n & 15);
        const int kb = kk * 16 + ((a >> 3) & 1) * 8 + 2 * (lane & 3);
        float w0, w1;
        if (s < 9) {
            const float* bp = Wt + ((size_t)s * CIN + kb) * NC + jcol;
            w0 = bp[0]; w1 = bp[NC];
        } else {
            const int u = s - 9, k9 = u >> 1, c0 = (u & 1) * 32;
            const float* bp = Ut + ((size_t)k9 * F_ + c0 + kb) * NC + jcol;
            w0 = bp[0]; w1 = bp[NC];
        }
        __half2 h2 = __floats2half2_rn(w0, w1);
        r[jm] = *(uint32_t*)&h2;
    }
    g_bf[s][wn][idx][lane] = make_uint4(r[0], r[1], r[2], r[3]);
}

// One ConvLSTM timestep. CTA: 8x8 pixels (M=64) x N=256, 8 warps (2m x 4n).
// Persistent halos; B via CTA-level cp.async double buffer prefetched
// ~1.5 slices ahead; consumption by distance-2 LDS ring; 2 bars/slice.
template<bool FIRST>
__global__ __launch_bounds__(256, 2)
void step_mma(const float* __restrict__ bias, int t, int hsel,
              float* __restrict__ out, int last)
{
    extern __shared__ __align__(16) char sm[];

    const int tid  = threadIdx.x;
    const int lane = tid & 31;
    const int w    = tid >> 5;
    const int warp_m = w & 1;
    const int warp_n = w >> 1;
    const int b  = blockIdx.z;
    const int y0 = blockIdx.y * 8;
    const int x0 = blockIdx.x * 8;
    const int NS = FIRST ? 9 : NSL;

    const __half* xframe = g_xh + (size_t)(b * T_ + t) * H_ * W_ * CIN;
    const __half* hframe = g_hh[hsel] + (size_t)b * H_ * W_ * F_;

    const uint32_t sb = smem_u32(sm);
    // CTA-level B copy: thread tid owns 64 B (4 x 16B) of each slice
    const uint64_t bsrc0 = gaddr(g_bf) + (uint64_t)tid * 64u;
    const uint32_t bdst0 = sb + SM_B + (uint32_t)tid * 64u;

    // prologue: slices 0 and 1 in flight (overlap with halo staging)
    {
        #pragma unroll
        for (int k = 0; k < 4; ++k) CP16(bdst0 + k * 16, bsrc0 + k * 16);
        CP_COMMIT();
        if (NS > 1) {
            #pragma unroll
            for (int k = 0; k < 4; ++k)
                CP16(bdst0 + BSLICE + k * 16, bsrc0 + BSLICE + k * 16);
        }
        CP_COMMIT();
    }

    // ---- stage halos once ----
    for (int j = tid; j < 400; j += 256) {            // x: 100 px * 4 chunks
        const int p = j >> 2, q = j & 3;
        const int gy = y0 + p / 10 - 1, gx = x0 + p % 10 - 1;
        uint4 v = make_uint4(0u, 0u, 0u, 0u);
        if ((unsigned)gy < H_ && (unsigned)gx < W_)
            v = *(const uint4*)(xframe + ((size_t)gy * W_ + gx) * CIN + q * 8);
        *(uint4*)(sm + SM_XH + p * XH_PITCH + q * 16) = v;
    }
    if (!FIRST) {
        for (int j = tid; j < 800; j += 256) {        // h: 100 px * 8 chunks
            const int p = j >> 3, q = j & 7;
            const int gy = y0 + p / 10 - 1, gx = x0 + p % 10 - 1;
            uint4 v = make_uint4(0u, 0u, 0u, 0u);
            if ((unsigned)gy < H_ && (unsigned)gx < W_)
                v = *(const uint4*)(hframe + ((size_t)gy * W_ + gx) * F_ + q * 8);
            *(uint4*)(sm + SM_HH + p * HH_PITCH + q * 16) = v;
        }
    }

    // ---- per-lane A ldmatrix base addresses ----
    const int hi  = (lane >> 4) << 4;
    const int m0  = warp_m * 32 + (lane & 15);
    const int m1  = m0 + 16;
    const int f0p = (m0 >> 3) * 10 + (m0 & 7);
    const int f1p = (m1 >> 3) * 10 + (m1 & 7);
    const uint32_t aAx0 = sb + SM_XH + f0p * XH_PITCH + hi;
    const uint32_t aAx1 = sb + SM_XH + f1p * XH_PITCH + hi;
    const uint32_t aAh0 = sb + SM_HH + f0p * HH_PITCH + hi;
    const uint32_t aAh1 = sb + SM_HH + f1p * HH_PITCH + hi;
    const uint32_t bread0 = sb + SM_B + (uint32_t)warp_n * 4096u
                          + (uint32_t)lane * 16u;

    float d[2][8][4];
    #pragma unroll
    for (int mt = 0; mt < 2; ++mt)
        #pragma unroll
        for (int nt = 0; nt < 8; ++nt)
            #pragma unroll
            for (int c = 0; c < 4; ++c) d[mt][nt][c] = 0.f;

    for (int s = 0; s < NS; ++s) {
        // select A source + shift offset for this slice
        uint32_t A0, A1, soff;
        if (FIRST || s < 9) {
            const int ky = s / 3, kx = s - 3 * (s / 3);
            A0 = aAx0; A1 = aAx1;
            soff = (uint32_t)(ky * 10 + kx) * XH_PITCH;
        } else {
            const int u = s - 9, k9 = u >> 1, c0 = (u & 1) * 32;
            const int ky = k9 / 3, kx = k9 - 3 * (k9 / 3);
            A0 = aAh0; A1 = aAh1;
            soff = (uint32_t)(ky * 10 + kx) * HH_PITCH + c0 * 2;
        }

        // slice s's group is 2 commits back -> wait <=1 pending
        if (s + 2 <= NS) CP_WAIT1(); else CP_WAIT0();
        __syncthreads();   // data visible to all; all ready to consume s

        const uint32_t bbase = bread0 + (s & 1) * BSLICE;
        uint4 bb[4];
        LDSV4(bb[0], bbase + 0 * 512);
        LDSV4(bb[1], bbase + 1 * 512);
        #pragma unroll
        for (int kk = 0; kk < 2; ++kk) {
            uint32_t a0r[4], a1r[4];
            LDSM4(a0r[0], a0r[1], a0r[2], a0r[3], A0 + soff + kk * 32);
            LDSM4(a1r[0], a1r[1], a1r[2], a1r[3], A1 + soff + kk * 32);
            #pragma unroll
            for (int p = 0; p < 4; ++p) {
                const int idx = kk * 4 + p;
                if (idx + 2 < 8) LDSV4(bb[(idx + 2) & 3], bbase + (idx + 2) * 512);
                uint4 cb = bb[idx & 3];
                MMA16816(d[0][2 * p + 0], a0r[0], a0r[1], a0r[2], a0r[3], cb.x, cb.y);
                MMA16816(d[0][2 * p + 1], a0r[0], a0r[1], a0r[2], a0r[3], cb.z, cb.w);
                MMA16816(d[1][2 * p + 0], a1r[0], a1r[1], a1r[2], a1r[3], cb.x, cb.y);
                MMA16816(d[1][2 * p + 1], a1r[0], a1r[1], a1r[2], a1r[3], cb.z, cb.w);
            }
        }
        __syncthreads();   // all done consuming s -> safe to refill buf[s&1]

        if (s + 2 < NS) {
            const uint64_t nsrc = bsrc0 + (uint64_t)(s + 2) * BSLICE;
            const uint32_t ndst = bdst0 + (s & 1) * BSLICE;
            #pragma unroll
            for (int k = 0; k < 4; ++k) CP16(ndst + k * 16, nsrc + k * 16);
            CP_COMMIT();
        } else {
            CP_COMMIT();   // empty group keeps the wait-count arithmetic uniform
        }
    }

    // ================= fused LSTM epilogue (verified layout) ==============
    __half* hhout = g_hh[hsel ^ 1];
    const int fq = 2 * (lane & 3);

    #pragma unroll
    for (int mt = 0; mt < 2; ++mt) {
        #pragma unroll
        for (int rh = 0; rh < 2; ++rh) {
            const int m  = warp_m * 32 + mt * 16 + rh * 8 + (lane >> 2);
            const int py = m >> 3, px = m & 7;
            const size_t pix =
                (((size_t)b * H_ + (y0 + py)) * W_ + (x0 + px)) * F_;
            #pragma unroll
            for (int t1 = 0; t1 < 2; ++t1) {
                const int f0 = warp_n * 16 + t1 * 8 + fq;
                float zi0 = d[mt][0 + t1][rh * 2 + 0], zi1 = d[mt][0 + t1][rh * 2 + 1];
                float zf0 = d[mt][2 + t1][rh * 2 + 0], zf1 = d[mt][2 + t1][rh * 2 + 1];
                float zc0 = d[mt][4 + t1][rh * 2 + 0], zc1 = d[mt][4 + t1][rh * 2 + 1];
                float zo0 = d[mt][6 + t1][rh * 2 + 0], zo1 = d[mt][6 + t1][rh * 2 + 1];

                float2 co = make_float2(0.f, 0.f);
                if (!FIRST) co = *(const float2*)&g_c[pix + f0];

                float ig0 = hsig(zi0 + bias[f0]);
                float fg0 = hsig(zf0 + bias[64 + f0]);
                float zz0 =      zc0 + bias[128 + f0];
                float og0 = hsig(zo0 + bias[192 + f0]);
                float cn0 = fg0 * co.x + ig0 * fmaxf(zz0, 0.f);
                float hn0 = og0 * fmaxf(cn0, 0.f);

                float ig1 = hsig(zi1 + bias[f0 + 1]);
                float fg1 = hsig(zf1 + bias[65 + f0]);
                float zz1 =      zc1 + bias[129 + f0];
                float og1 = hsig(zo1 + bias[193 + f0]);
                float cn1 = fg1 * co.y + ig1 * fmaxf(zz1, 0.f);
                float hn1 = og1 * fmaxf(cn1, 0.f);

                if (!last) {
                    *(float2*)&g_c[pix + f0] = make_float2(cn0, cn1);
                    *(__half2*)&hhout[pix + f0] = __floats2half2_rn(hn0, hn1);
                } else {
                    *(float2*)&out[pix + f0] = make_float2(hn0, hn1);
                }
            }
        }
    }
}

extern "C" void kernel_launch(void* const* d_in, const int* in_sizes, int n_in,
                              void* d_out, int out_size)
{
    const float* x = nullptr; const float* Wt = nullptr;
    const float* Ut = nullptr; const float* bias = nullptr;
    for (int i = 0; i < n_in; ++i) {
        switch (in_sizes[i]) {
            case B_*T_*H_*W_*CIN: x    = (const float*)d_in[i]; break;
            case 3*3*CIN*NC:      Wt   = (const float*)d_in[i]; break;
            case 3*3*F_*NC:       Ut   = (const float*)d_in[i]; break;
            case NC:              bias = (const float*)d_in[i]; break;
        }
    }
    if (!x || !Wt || !Ut || !bias) {
        x = (const float*)d_in[0]; Wt = (const float*)d_in[1];
        Ut = (const float*)d_in[2]; bias = (const float*)d_in[3];
    }
    float* out = (float*)d_out;

    prep_x<<<(B_ * T_ * H_ * W_ * CIN) / 1024, 256>>>(x);
    prep_bf<<<dim3(NSL, 4), 256>>>(Wt, Ut);

    cudaFuncSetAttribute(step_mma<true>,
                         cudaFuncAttributeMaxDynamicSharedMemorySize, SM_TOT);
    cudaFuncSetAttribute(step_mma<false>,
                         cudaFuncAttributeMaxDynamicSharedMemorySize, SM_TOT);

    dim3 grid(W_ / 8, H_ / 8, B_);    // 512 CTAs
    dim3 block(256);

    step_mma<true><<<grid, block, SM_TOT>>>(bias, 0, 0, out, 0);
    for (int t = 1; t < T_; ++t) {
        int last = (t == T_ - 1);
        step_mma<false><<<grid, block, SM_TOT>>>(bias, t, t & 1, out, last);
    }
}

// round 13
// speedup vs baseline: 1.2915x; 1.2915x over previous
#include <cuda_runtime.h>
#include <cuda_fp16.h>
#include <cstdint>

#define B_   8
#define T_   16
#define H_   64
#define W_   64
#define CIN  32
#define F_   64
#define NC   256          // 4*F gates [i,f,c,o]
#define NSL  27           // 9 x-slices + 18 h-slices (K=32 each)

// Persistent state. h in fp16 (feeds fp16 MMA), c in fp32.
__device__ __half g_hh[2][B_ * H_ * W_ * F_];
__device__ float  g_c[B_ * H_ * W_ * F_];
// x pre-converted to fp16
__device__ __half g_xh[B_ * T_ * H_ * W_ * CIN];
// Weights pre-packed in MMA B-fragment order (verified R5/R7):
// [slice][warp_n][idx = kk*4+p][lane] -> uint4   (16 KB per slice)
__device__ uint4 g_bf[NSL][4][8][32];

#define XH_PITCH 80     // bytes per halo pixel row (x: 64B data + pad)
#define HH_PITCH 144    // bytes per halo pixel row (h: 128B data + pad)
#define SM_XH 0
#define SM_HH 8000                    // 100*80
#define SM_B  (8000 + 100 * 144)      // 22400
#define SM_TOT (SM_B + 8 * 2 * 4096)  // 87936 B (8 warps x double 4KB B buf)

__device__ __forceinline__ float hsig(float x) {
    return __saturatef((x + 3.0f) * 0.16666667f);  // hard_sigmoid
}
__device__ __forceinline__ uint32_t smem_u32(const void* p) {
    uint32_t a;
    asm("{ .reg .u64 t; cvta.to.shared.u64 t, %1; cvt.u32.u64 %0, t; }"
        : "=r"(a) : "l"(p));
    return a;
}
__device__ __forceinline__ uint64_t gaddr(const void* p) {
    uint64_t a;
    asm("cvta.to.global.u64 %0, %1;" : "=l"(a) : "l"(p));
    return a;
}

#define CP16(dst, src) \
    asm volatile("cp.async.ca.shared.global [%0], [%1], 16, 16;" \
                 :: "r"(dst), "l"(src) : "memory")
#define CP_COMMIT() asm volatile("cp.async.commit_group;" ::: "memory")
#define CP_WAIT0()  asm volatile("cp.async.wait_group 0;" ::: "memory")

#define LDSV4(v, addr) \
    asm volatile("ld.shared.v4.u32 {%0,%1,%2,%3}, [%4];" \
        : "=r"((v).x), "=r"((v).y), "=r"((v).z), "=r"((v).w) : "r"(addr))

#define LDSM4(r0, r1, r2, r3, addr) \
    asm volatile("ldmatrix.sync.aligned.m8n8.x4.shared.b16 {%0,%1,%2,%3}, [%4];" \
        : "=r"(r0), "=r"(r1), "=r"(r2), "=r"(r3) : "r"(addr))

#define MMA16816(d, a0, a1, a2, a3, b0, b1) \
    asm volatile("mma.sync.aligned.m16n8k16.row.col.f32.f16.f16.f32 " \
        "{%0,%1,%2,%3}, {%4,%5,%6,%7}, {%8,%9}, {%0,%1,%2,%3};" \
        : "+f"((d)[0]), "+f"((d)[1]), "+f"((d)[2]), "+f"((d)[3]) \
        : "r"(a0), "r"(a1), "r"(a2), "r"(a3), "r"(b0), "r"(b1))

// ---- one-time preps ----
__global__ void prep_x(const float* __restrict__ x) {
    size_t i = ((size_t)blockIdx.x * 256 + threadIdx.x) * 4;
    float4 v = *(const float4*)(x + i);
    __half2 h2[2];
    h2[0] = __floats2half2_rn(v.x, v.y);
    h2[1] = __floats2half2_rn(v.z, v.w);
    *(uint2*)&g_xh[i] = *(uint2*)h2;
}

// Pack weights into B-fragment order (verified R5/R7).
__global__ void prep_bf(const float* __restrict__ Wt,
                        const float* __restrict__ Ut) {
    const int s    = blockIdx.x;          // 0..26
    const int wn   = blockIdx.y;          // 0..3
    const int idx  = threadIdx.x >> 5;    // 0..7
    const int lane = threadIdx.x & 31;
    const int kk = idx >> 2, p = idx & 3;

    uint32_t r[4];
    #pragma unroll
    for (int jm = 0; jm < 4; ++jm) {
        const int a  = 8 * jm + (lane >> 2);
        const int n  = wn * 64 + p * 16 + ((a >> 4) << 3) + (a & 7);
        const int jcol = ((n >> 4) & 3) * 64 + (n >> 6) * 16 + (n & 15);
        const int kb = kk * 16 + ((a >> 3) & 1) * 8 + 2 * (lane & 3);
        float w0, w1;
        if (s < 9) {
            const float* bp = Wt + ((size_t)s * CIN + kb) * NC + jcol;
            w0 = bp[0]; w1 = bp[NC];
        } else {
            const int u = s - 9, k9 = u >> 1, c0 = (u & 1) * 32;
            const float* bp = Ut + ((size_t)k9 * F_ + c0 + kb) * NC + jcol;
            w0 = bp[0]; w1 = bp[NC];
        }
        __half2 h2 = __floats2half2_rn(w0, w1);
        r[jm] = *(uint32_t*)&h2;
    }
    g_bf[s][wn][idx][lane] = make_uint4(r[0], r[1], r[2], r[3]);
}

// One ConvLSTM timestep. CTA: 8x8 pixels (M=64) x N=256, 8 warps (2m x 4n).
// Persistent halos; B via warp-private cp.async double buffer, distance-1,
// lane-self-consumed (cp.async.wait_group only, NO barriers in mainloop).
template<bool FIRST>
__global__ __launch_bounds__(256, 2)
void step_mma(const float* __restrict__ bias, int t, int hsel,
              float* __restrict__ out, int last)
{
    extern __shared__ __align__(16) char sm[];

    const int tid  = threadIdx.x;
    const int lane = tid & 31;
    const int w    = tid >> 5;
    const int warp_m = w & 1;
    const int warp_n = w >> 1;
    const int b  = blockIdx.z;
    const int y0 = blockIdx.y * 8;
    const int x0 = blockIdx.x * 8;
    const int NS = FIRST ? 9 : NSL;

    const __half* xframe = g_xh + (size_t)(b * T_ + t) * H_ * W_ * CIN;
    const __half* hframe = g_hh[hsel] + (size_t)b * H_ * W_ * F_;

    const uint32_t sb = smem_u32(sm);
    // warp-private B buffer: lane owns 16B of each of 8 fragment groups
    const uint32_t bdst0 = sb + SM_B + (uint32_t)w * 8192u + (uint32_t)lane * 16u;
    const uint64_t bsrc  = gaddr(&g_bf[0][warp_n][0][lane]);

    // prologue: slice 0 copy in flight (covered by halo staging)
    {
        #pragma unroll
        for (int k = 0; k < 8; ++k) CP16(bdst0 + k * 512u, bsrc + k * 512u);
        CP_COMMIT();
    }

    // ---- stage halos once ----
    for (int j = tid; j < 400; j += 256) {            // x: 100 px * 4 chunks
        const int p = j >> 2, q = j & 3;
        const int gy = y0 + p / 10 - 1, gx = x0 + p % 10 - 1;
        uint4 v = make_uint4(0u, 0u, 0u, 0u);
        if ((unsigned)gy < H_ && (unsigned)gx < W_)
            v = *(const uint4*)(xframe + ((size_t)gy * W_ + gx) * CIN + q * 8);
        *(uint4*)(sm + SM_XH + p * XH_PITCH + q * 16) = v;
    }
    if (!FIRST) {
        for (int j = tid; j < 800; j += 256) {        // h: 100 px * 8 chunks
            const int p = j >> 3, q = j & 7;
            const int gy = y0 + p / 10 - 1, gx = x0 + p % 10 - 1;
            uint4 v = make_uint4(0u, 0u, 0u, 0u);
            if ((unsigned)gy < H_ && (unsigned)gx < W_)
                v = *(const uint4*)(hframe + ((size_t)gy * W_ + gx) * F_ + q * 8);
            *(uint4*)(sm + SM_HH + p * HH_PITCH + q * 16) = v;
        }
    }
    __syncthreads();   // halos ready — the only block barrier before epilogue

    // ---- per-lane A ldmatrix base addresses ----
    const int hi  = (lane >> 4) << 4;
    const int m0  = warp_m * 32 + (lane & 15);
    const int m1  = m0 + 16;
    const int f0p = (m0 >> 3) * 10 + (m0 & 7);
    const int f1p = (m1 >> 3) * 10 + (m1 & 7);
    const uint32_t aAx0 = sb + SM_XH + f0p * XH_PITCH + hi;
    const uint32_t aAx1 = sb + SM_XH + f1p * XH_PITCH + hi;
    const uint32_t aAh0 = sb + SM_HH + f0p * HH_PITCH + hi;
    const uint32_t aAh1 = sb + SM_HH + f1p * HH_PITCH + hi;

    float d[2][8][4];
    #pragma unroll
    for (int mt = 0; mt < 2; ++mt)
        #pragma unroll
        for (int nt = 0; nt < 8; ++nt)
            #pragma unroll
            for (int c = 0; c < 4; ++c) d[mt][nt][c] = 0.f;

    #define SLICE_BODY(A0, A1, SOFF)                                          \
    do {                                                                      \
        CP_WAIT0();   /* slice s's copy (committed 1 slice ago) complete */   \
        if (s + 1 < NS) {   /* launch copy for s+1 into the other buffer */   \
            const uint64_t nsrc = bsrc + (uint64_t)(s + 1) * 16384u;          \
            const uint32_t ndst = bdst0 + ((s + 1) & 1) * 4096u;              \
            _Pragma("unroll")                                                 \
            for (int k2 = 0; k2 < 8; ++k2)                                    \
                CP16(ndst + k2 * 512u, nsrc + (uint64_t)k2 * 512u);           \
            CP_COMMIT();                                                      \
        }                                                                     \
        const uint32_t bbase = bdst0 + (s & 1) * 4096u;                       \
        uint4 bb[4];                                                          \
        LDSV4(bb[0], bbase + 0 * 512);                                        \
        LDSV4(bb[1], bbase + 1 * 512);                                        \
        _Pragma("unroll")                                                     \
        for (int kk = 0; kk < 2; ++kk) {                                      \
            uint32_t a0r[4], a1r[4];                                          \
            LDSM4(a0r[0], a0r[1], a0r[2], a0r[3], (A0) + (SOFF) + kk * 32);   \
            LDSM4(a1r[0], a1r[1], a1r[2], a1r[3], (A1) + (SOFF) + kk * 32);   \
            _Pragma("unroll")                                                 \
            for (int p = 0; p < 4; ++p) {                                     \
                const int idx = kk * 4 + p;                                   \
                if (idx + 2 < 8) LDSV4(bb[(idx + 2) & 3], bbase + (idx + 2) * 512); \
                uint4 cb = bb[idx & 3];                                       \
                MMA16816(d[0][2 * p + 0], a0r[0], a0r[1], a0r[2], a0r[3], cb.x, cb.y); \
                MMA16816(d[0][2 * p + 1], a0r[0], a0r[1], a0r[2], a0r[3], cb.z, cb.w); \
                MMA16816(d[1][2 * p + 0], a1r[0], a1r[1], a1r[2], a1r[3], cb.x, cb.y); \
                MMA16816(d[1][2 * p + 1], a1r[0], a1r[1], a1r[2], a1r[3], cb.z, cb.w); \
            }                                                                 \
        }                                                                     \
    } while (0)

    // x-conv slices
    for (int s = 0; s < 9; ++s) {
        const int ky = s / 3, kx = s - 3 * (s / 3);
        const uint32_t soff = (uint32_t)(ky * 10 + kx) * XH_PITCH;
        SLICE_BODY(aAx0, aAx1, soff);
    }
    // h-conv slices
    if (!FIRST) {
        for (int s = 9; s < NSL; ++s) {
            const int u = s - 9, k9 = u >> 1, c0 = (u & 1) * 32;
            const int ky = k9 / 3, kx = k9 - 3 * (k9 / 3);
            const uint32_t soff = (uint32_t)(ky * 10 + kx) * HH_PITCH + c0 * 2;
            SLICE_BODY(aAh0, aAh1, soff);
        }
    }
    #undef SLICE_BODY

    // ================= fused LSTM epilogue (verified layout) ==============
    __half* hhout = g_hh[hsel ^ 1];
    const int fq = 2 * (lane & 3);

    #pragma unroll
    for (int mt = 0; mt < 2; ++mt) {
        #pragma unroll
        for (int rh = 0; rh < 2; ++rh) {
            const int m  = warp_m * 32 + mt * 16 + rh * 8 + (lane >> 2);
            const int py = m >> 3, px = m & 7;
            const size_t pix =
                (((size_t)b * H_ + (y0 + py)) * W_ + (x0 + px)) * F_;
            #pragma unroll
            for (int t1 = 0; t1 < 2; ++t1) {
                const int f0 = warp_n * 16 + t1 * 8 + fq;
                float zi0 = d[mt][0 + t1][rh * 2 + 0], zi1 = d[mt][0 + t1][rh * 2 + 1];
                float zf0 = d[mt][2 + t1][rh * 2 + 0], zf1 = d[mt][2 + t1][rh * 2 + 1];
                float zc0 = d[mt][4 + t1][rh * 2 + 0], zc1 = d[mt][4 + t1][rh * 2 + 1];
                float zo0 = d[mt][6 + t1][rh * 2 + 0], zo1 = d[mt][6 + t1][rh * 2 + 1];

                float2 co = make_float2(0.f, 0.f);
                if (!FIRST) co = *(const float2*)&g_c[pix + f0];

                float ig0 = hsig(zi0 + bias[f0]);
                float fg0 = hsig(zf0 + bias[64 + f0]);
                float zz0 =      zc0 + bias[128 + f0];
                float og0 = hsig(zo0 + bias[192 + f0]);
                float cn0 = fg0 * co.x + ig0 * fmaxf(zz0, 0.f);
                float hn0 = og0 * fmaxf(cn0, 0.f);

                float ig1 = hsig(zi1 + bias[f0 + 1]);
                float fg1 = hsig(zf1 + bias[65 + f0]);
                float zz1 =      zc1 + bias[129 + f0];
                float og1 = hsig(zo1 + bias[193 + f0]);
                float cn1 = fg1 * co.y + ig1 * fmaxf(zz1, 0.f);
                float hn1 = og1 * fmaxf(cn1, 0.f);

                if (!last) {
                    *(float2*)&g_c[pix + f0] = make_float2(cn0, cn1);
                    *(__half2*)&hhout[pix + f0] = __floats2half2_rn(hn0, hn1);
                } else {
                    *(float2*)&out[pix + f0] = make_float2(hn0, hn1);
                }
            }
        }
    }
}

extern "C" void kernel_launch(void* const* d_in, const int* in_sizes, int n_in,
                              void* d_out, int out_size)
{
    const float* x = nullptr; const float* Wt = nullptr;
    const float* Ut = nullptr; const float* bias = nullptr;
    for (int i = 0; i < n_in; ++i) {
        switch (in_sizes[i]) {
            case B_*T_*H_*W_*CIN: x    = (const float*)d_in[i]; break;
            case 3*3*CIN*NC:      Wt   = (const float*)d_in[i]; break;
            case 3*3*F_*NC:       Ut   = (const float*)d_in[i]; break;
            case NC:              bias = (const float*)d_in[i]; break;
        }
    }
    if (!x || !Wt || !Ut || !bias) {
        x = (const float*)d_in[0]; Wt = (const float*)d_in[1];
        Ut = (const float*)d_in[2]; bias = (const float*)d_in[3];
    }
    float* out = (float*)d_out;

    prep_x<<<(B_ * T_ * H_ * W_ * CIN) / 1024, 256>>>(x);
    prep_bf<<<dim3(NSL, 4), 256>>>(Wt, Ut);

    cudaFuncSetAttribute(step_mma<true>,
                         cudaFuncAttributeMaxDynamicSharedMemorySize, SM_TOT);
    cudaFuncSetAttribute(step_mma<false>,
                         cudaFuncAttributeMaxDynamicSharedMemorySize, SM_TOT);

    dim3 grid(W_ / 8, H_ / 8, B_);    // 512 CTAs
    dim3 block(256);

    step_mma<true><<<grid, block, SM_TOT>>>(bias, 0, 0, out, 0);
    for (int t = 1; t < T_; ++t) {
        int last = (t == T_ - 1);
        step_mma<false><<<grid, block, SM_TOT>>>(bias, t, t & 1, out, last);
    }
}

// round 14
// speedup vs baseline: 1.5336x; 1.1874x over previous
#include <cuda_runtime.h>
#include <cuda_fp16.h>
#include <cstdint>

#define B_   8
#define T_   16
#define H_   64
#define W_   64
#define CIN  32
#define F_   64
#define NC   256          // 4*F gates [i,f,c,o]
#define NSL  27           // 9 x-slices + 18 h-slices (K=32 each)

// Persistent state. h in fp16 (feeds fp16 MMA), c in fp32.
__device__ __half g_hh[2][B_ * H_ * W_ * F_];
__device__ float  g_c[B_ * H_ * W_ * F_];
// x pre-converted to fp16
__device__ __half g_xh[B_ * T_ * H_ * W_ * CIN];
// Weights pre-packed in MMA B-fragment order (verified R5/R7):
// [slice][warp_n][idx = kk*4+p][lane] -> uint4
__device__ uint4 g_bf[NSL][4][8][32];

#define XH_PITCH 80     // bytes per halo pixel row (x: 64B data + pad)
#define HH_PITCH 144    // bytes per halo pixel row (h: 128B data + pad)
#define SM_XH 0
#define SM_HH 8000      // 100*80
#define SM_TOT (8000 + 100 * 144)   // 22400 B

__device__ __forceinline__ float hsig(float x) {
    return __saturatef((x + 3.0f) * 0.16666667f);  // hard_sigmoid
}
__device__ __forceinline__ uint32_t smem_u32(const void* p) {
    uint32_t a;
    asm("{ .reg .u64 t; cvta.to.shared.u64 t, %1; cvt.u32.u64 %0, t; }"
        : "=r"(a) : "l"(p));
    return a;
}

#define LDSM4(r0, r1, r2, r3, addr) \
    asm volatile("ldmatrix.sync.aligned.m8n8.x4.shared.b16 {%0,%1,%2,%3}, [%4];" \
        : "=r"(r0), "=r"(r1), "=r"(r2), "=r"(r3) : "r"(addr))

#define MMA16816(d, a0, a1, a2, a3, b0, b1) \
    asm volatile("mma.sync.aligned.m16n8k16.row.col.f32.f16.f16.f32 " \
        "{%0,%1,%2,%3}, {%4,%5,%6,%7}, {%8,%9}, {%0,%1,%2,%3};" \
        : "+f"((d)[0]), "+f"((d)[1]), "+f"((d)[2]), "+f"((d)[3]) \
        : "r"(a0), "r"(a1), "r"(a2), "r"(a3), "r"(b0), "r"(b1))

// ---- one-time preps ----
__global__ void prep_x(const float* __restrict__ x) {
    size_t i = ((size_t)blockIdx.x * 256 + threadIdx.x) * 4;
    float4 v = *(const float4*)(x + i);
    __half2 h2[2];
    h2[0] = __floats2half2_rn(v.x, v.y);
    h2[1] = __floats2half2_rn(v.z, v.w);
    *(uint2*)&g_xh[i] = *(uint2*)h2;
}

// Pack weights into B-fragment order (verified R5/R7).
__global__ void prep_bf(const float* __restrict__ Wt,
                        const float* __restrict__ Ut) {
    const int s    = blockIdx.x;          // 0..26
    const int wn   = blockIdx.y;          // 0..3
    const int idx  = threadIdx.x >> 5;    // 0..7
    const int lane = threadIdx.x & 31;
    const int kk = idx >> 2, p = idx & 3;

    uint32_t r[4];
    #pragma unroll
    for (int jm = 0; jm < 4; ++jm) {
        const int a  = 8 * jm + (lane >> 2);
        const int n  = wn * 64 + p * 16 + ((a >> 4) << 3) + (a & 7);
        const int jcol = ((n >> 4) & 3) * 64 + (n >> 6) * 16 + (n & 15);
        const int kb = kk * 16 + ((a >> 3) & 1) * 8 + 2 * (lane & 3);
        float w0, w1;
        if (s < 9) {
            const float* bp = Wt + ((size_t)s * CIN + kb) * NC + jcol;
            w0 = bp[0]; w1 = bp[NC];
        } else {
            const int u = s - 9, k9 = u >> 1, c0 = (u & 1) * 32;
            const float* bp = Ut + ((size_t)k9 * F_ + c0 + kb) * NC + jcol;
            w0 = bp[0]; w1 = bp[NC];
        }
        __half2 h2 = __floats2half2_rn(w0, w1);
        r[jm] = *(uint32_t*)&h2;
    }
    g_bf[s][wn][idx][lane] = make_uint4(r[0], r[1], r[2], r[3]);
}

// One ConvLSTM timestep. CTA: 8x8 pixels (M=64) x N=256, 8 warps (2m x 4n).
// Persistent halos; zero barriers in mainloop; B via distance-2 LDG ring.
// NEW: per-warp slice ROTATION (warp w starts at slice w*3) desynchronizes
// warp phases so LDSM/LDG of one warp overlaps MMA of another.
template<bool FIRST>
__global__ __launch_bounds__(256, 2)
void step_mma(const float* __restrict__ bias, int t, int hsel,
              float* __restrict__ out, int last)
{
    __shared__ __align__(16) char sm[SM_TOT];

    const int tid  = threadIdx.x;
    const int lane = tid & 31;
    const int w    = tid >> 5;
    const int warp_m = w & 1;
    const int warp_n = w >> 1;
    const int b  = blockIdx.z;
    const int y0 = blockIdx.y * 8;
    const int x0 = blockIdx.x * 8;

    const __half* xframe = g_xh + (size_t)(b * T_ + t) * H_ * W_ * CIN;
    const __half* hframe = g_hh[hsel] + (size_t)b * H_ * W_ * F_;

    // ---- stage halos once ----
    for (int j = tid; j < 400; j += 256) {            // x: 100 px * 4 chunks
        const int p = j >> 2, q = j & 3;
        const int gy = y0 + p / 10 - 1, gx = x0 + p % 10 - 1;
        uint4 v = make_uint4(0u, 0u, 0u, 0u);
        if ((unsigned)gy < H_ && (unsigned)gx < W_)
            v = *(const uint4*)(xframe + ((size_t)gy * W_ + gx) * CIN + q * 8);
        *(uint4*)(sm + SM_XH + p * XH_PITCH + q * 16) = v;
    }
    if (!FIRST) {
        for (int j = tid; j < 800; j += 256) {        // h: 100 px * 8 chunks
            const int p = j >> 3, q = j & 7;
            const int gy = y0 + p / 10 - 1, gx = x0 + p % 10 - 1;
            uint4 v = make_uint4(0u, 0u, 0u, 0u);
            if ((unsigned)gy < H_ && (unsigned)gx < W_)
                v = *(const uint4*)(hframe + ((size_t)gy * W_ + gx) * F_ + q * 8);
            *(uint4*)(sm + SM_HH + p * HH_PITCH + q * 16) = v;
        }
    }
    __syncthreads();   // the only barrier before the epilogue

    // ---- per-lane A ldmatrix base addresses ----
    const uint32_t sb = smem_u32(sm);
    const int hi  = (lane >> 4) << 4;
    const int m0  = warp_m * 32 + (lane & 15);
    const int m1  = m0 + 16;
    const int f0p = (m0 >> 3) * 10 + (m0 & 7);
    const int f1p = (m1 >> 3) * 10 + (m1 & 7);
    const uint32_t aAx0 = sb + SM_XH + f0p * XH_PITCH + hi;
    const uint32_t aAx1 = sb + SM_XH + f1p * XH_PITCH + hi;
    const uint32_t aAh0 = sb + SM_HH + f0p * HH_PITCH + hi;
    const uint32_t aAh1 = sb + SM_HH + f1p * HH_PITCH + hi;

    float d[2][8][4];
    #pragma unroll
    for (int mt = 0; mt < 2; ++mt)
        #pragma unroll
        for (int nt = 0; nt < 8; ++nt)
            #pragma unroll
            for (int c = 0; c < 4; ++c) d[mt][nt][c] = 0.f;

    const int NS = FIRST ? 9 : NSL;
    const int off = FIRST ? w : (w * 3);   // per-warp rotation start
    int s = off;

    // B fragment pointers (uint4 units; slice stride = 1024 uint4 = 16 KB)
    const uint4* bfb = &g_bf[0][warp_n][0][lane];
    const uint4* bp  = bfb + (size_t)s * 1024;
    uint4 bb[4];
    bb[0] = bp[0];
    bb[1] = bp[32];

    for (int i = 0; i < NS; ++i) {
        int ns2 = s + 1; if (ns2 == NS) ns2 = 0;            // rotated successor
        const uint4* bnp = (i + 1 < NS) ? (bfb + (size_t)ns2 * 1024) : bp;

        uint32_t A0, A1, soff;
        if (FIRST || s < 9) {
            const int ky = s / 3, kx = s - 3 * (s / 3);
            A0 = aAx0; A1 = aAx1;
            soff = (uint32_t)(ky * 10 + kx) * XH_PITCH;
        } else {
            const int u = s - 9, k9 = u >> 1, c0 = (u & 1) * 32;
            const int ky = k9 / 3, kx = k9 - 3 * (k9 / 3);
            A0 = aAh0; A1 = aAh1;
            soff = (uint32_t)(ky * 10 + kx) * HH_PITCH + c0 * 2;
        }

        #pragma unroll
        for (int kk = 0; kk < 2; ++kk) {
            uint32_t a0r[4], a1r[4];
            LDSM4(a0r[0], a0r[1], a0r[2], a0r[3], A0 + soff + kk * 32);
            LDSM4(a1r[0], a1r[1], a1r[2], a1r[3], A1 + soff + kk * 32);
            #pragma unroll
            for (int p = 0; p < 4; ++p) {
                const int idx = kk * 4 + p;
                const uint4* pf = (idx + 2 < 8) ? (bp + (idx + 2) * 32)
                                                : (bnp + (idx - 6) * 32);
                uint4 nb = *pf;
                uint4 cb = bb[p];
                MMA16816(d[0][2 * p + 0], a0r[0], a0r[1], a0r[2], a0r[3], cb.x, cb.y);
                MMA16816(d[0][2 * p + 1], a0r[0], a0r[1], a0r[2], a0r[3], cb.z, cb.w);
                MMA16816(d[1][2 * p + 0], a1r[0], a1r[1], a1r[2], a1r[3], cb.x, cb.y);
                MMA16816(d[1][2 * p + 1], a1r[0], a1r[1], a1r[2], a1r[3], cb.z, cb.w);
                bb[(p + 2) & 3] = nb;
            }
        }
        bp = bnp;
        s = ns2;
    }

    // ================= fused LSTM epilogue (verified layout) ==============
    __half* hhout = g_hh[hsel ^ 1];
    const int fq = 2 * (lane & 3);

    #pragma unroll
    for (int mt = 0; mt < 2; ++mt) {
        #pragma unroll
        for (int rh = 0; rh < 2; ++rh) {
            const int m  = warp_m * 32 + mt * 16 + rh * 8 + (lane >> 2);
            const int py = m >> 3, px = m & 7;
            const size_t pix =
                (((size_t)b * H_ + (y0 + py)) * W_ + (x0 + px)) * F_;
            #pragma unroll
            for (int t1 = 0; t1 < 2; ++t1) {
                const int f0 = warp_n * 16 + t1 * 8 + fq;
                float zi0 = d[mt][0 + t1][rh * 2 + 0], zi1 = d[mt][0 + t1][rh * 2 + 1];
                float zf0 = d[mt][2 + t1][rh * 2 + 0], zf1 = d[mt][2 + t1][rh * 2 + 1];
                float zc0 = d[mt][4 + t1][rh * 2 + 0], zc1 = d[mt][4 + t1][rh * 2 + 1];
                float zo0 = d[mt][6 + t1][rh * 2 + 0], zo1 = d[mt][6 + t1][rh * 2 + 1];

                float2 co = make_float2(0.f, 0.f);
                if (!FIRST) co = *(const float2*)&g_c[pix + f0];

                float ig0 = hsig(zi0 + bias[f0]);
                float fg0 = hsig(zf0 + bias[64 + f0]);
                float zz0 =      zc0 + bias[128 + f0];
                float og0 = hsig(zo0 + bias[192 + f0]);
                float cn0 = fg0 * co.x + ig0 * fmaxf(zz0, 0.f);
                float hn0 = og0 * fmaxf(cn0, 0.f);

                float ig1 = hsig(zi1 + bias[f0 + 1]);
                float fg1 = hsig(zf1 + bias[65 + f0]);
                float zz1 =      zc1 + bias[129 + f0];
                float og1 = hsig(zo1 + bias[193 + f0]);
                float cn1 = fg1 * co.y + ig1 * fmaxf(zz1, 0.f);
                float hn1 = og1 * fmaxf(cn1, 0.f);

                if (!last) {
                    *(float2*)&g_c[pix + f0] = make_float2(cn0, cn1);
                    *(__half2*)&hhout[pix + f0] = __floats2half2_rn(hn0, hn1);
                } else {
                    *(float2*)&out[pix + f0] = make_float2(hn0, hn1);
                }
            }
        }
    }
}

extern "C" void kernel_launch(void* const* d_in, const int* in_sizes, int n_in,
                              void* d_out, int out_size)
{
    const float* x = nullptr; const float* Wt = nullptr;
    const float* Ut = nullptr; const float* bias = nullptr;
    for (int i = 0; i < n_in; ++i) {
        switch (in_sizes[i]) {
            case B_*T_*H_*W_*CIN: x    = (const float*)d_in[i]; break;
            case 3*3*CIN*NC:      Wt   = (const float*)d_in[i]; break;
            case 3*3*F_*NC:       Ut   = (const float*)d_in[i]; break;
            case NC:              bias = (const float*)d_in[i]; break;
        }
    }
    if (!x || !Wt || !Ut || !bias) {
        x = (const float*)d_in[0]; Wt = (const float*)d_in[1];
        Ut = (const float*)d_in[2]; bias = (const float*)d_in[3];
    }
    float* out = (float*)d_out;

    prep_x<<<(B_ * T_ * H_ * W_ * CIN) / 1024, 256>>>(x);
    prep_bf<<<dim3(NSL, 4), 256>>>(Wt, Ut);

    dim3 grid(W_ / 8, H_ / 8, B_);    // 512 CTAs
    dim3 block(256);

    step_mma<true><<<grid, block>>>(bias, 0, 0, out, 0);
    for (int t = 1; t < T_; ++t) {
        int last = (t == T_ - 1);
        step_mma<false><<<grid, block>>>(bias, t, t & 1, out, last);
    }
}

// round 15
// speedup vs baseline: 1.7620x; 1.1489x over previous
#include <cuda_runtime.h>
#include <cuda_fp16.h>
#include <cstdint>

#define B_   8
#define T_   16
#define H_   64
#define W_   64
#define CIN  32
#define F_   64
#define NC   256          // 4*F gates [i,f,c,o]
#define NSL  27           // 9 x-slices + 18 h-slices (K=32 each)

// Persistent state. h in fp16 (feeds fp16 MMA), c in fp32.
__device__ __half g_hh[2][B_ * H_ * W_ * F_];
__device__ float  g_c[B_ * H_ * W_ * F_];
// Weights pre-packed in MMA B-fragment order (verified R5/R7):
// [slice][warp_n][idx = kk*4+p][lane] -> uint4
__device__ uint4 g_bf[NSL][4][8][32];

#define XH_PITCH 80     // bytes per halo pixel row (x: 64B data + pad)
#define HH_PITCH 144    // bytes per halo pixel row (h: 128B data + pad)
#define SM_XH 0
#define SM_HH 8000      // 100*80
#define SM_TOT (8000 + 100 * 144)   // 22400 B

__device__ __forceinline__ float hsig(float x) {
    return __saturatef((x + 3.0f) * 0.16666667f);  // hard_sigmoid
}
__device__ __forceinline__ uint32_t smem_u32(const void* p) {
    uint32_t a;
    asm("{ .reg .u64 t; cvta.to.shared.u64 t, %1; cvt.u32.u64 %0, t; }"
        : "=r"(a) : "l"(p));
    return a;
}

#define LDSM4(r0, r1, r2, r3, addr) \
    asm volatile("ldmatrix.sync.aligned.m8n8.x4.shared.b16 {%0,%1,%2,%3}, [%4];" \
        : "=r"(r0), "=r"(r1), "=r"(r2), "=r"(r3) : "r"(addr))

#define MMA16816(d, a0, a1, a2, a3, b0, b1) \
    asm volatile("mma.sync.aligned.m16n8k16.row.col.f32.f16.f16.f32 " \
        "{%0,%1,%2,%3}, {%4,%5,%6,%7}, {%8,%9}, {%0,%1,%2,%3};" \
        : "+f"((d)[0]), "+f"((d)[1]), "+f"((d)[2]), "+f"((d)[3]) \
        : "r"(a0), "r"(a1), "r"(a2), "r"(a3), "r"(b0), "r"(b1))

// ---- one-time prep: pack weights into B-fragment order (verified R5/R7) ----
__global__ void prep_bf(const float* __restrict__ Wt,
                        const float* __restrict__ Ut) {
    const int s    = blockIdx.x;          // 0..26
    const int wn   = blockIdx.y;          // 0..3
    const int idx  = threadIdx.x >> 5;    // 0..7
    const int lane = threadIdx.x & 31;
    const int kk = idx >> 2, p = idx & 3;

    uint32_t r[4];
    #pragma unroll
    for (int jm = 0; jm < 4; ++jm) {
        const int a  = 8 * jm + (lane >> 2);
        const int n  = wn * 64 + p * 16 + ((a >> 4) << 3) + (a & 7);
        const int jcol = ((n >> 4) & 3) * 64 + (n >> 6) * 16 + (n & 15);
        const int kb = kk * 16 + ((a >> 3) & 1) * 8 + 2 * (lane & 3);
        float w0, w1;
        if (s < 9) {
            const float* bp = Wt + ((size_t)s * CIN + kb) * NC + jcol;
            w0 = bp[0]; w1 = bp[NC];
        } else {
            const int u = s - 9, k9 = u >> 1, c0 = (u & 1) * 32;
            const float* bp = Ut + ((size_t)k9 * F_ + c0 + kb) * NC + jcol;
            w0 = bp[0]; w1 = bp[NC];
        }
        __half2 h2 = __floats2half2_rn(w0, w1);
        r[jm] = *(uint32_t*)&h2;
    }
    g_bf[s][wn][idx][lane] = make_uint4(r[0], r[1], r[2], r[3]);
}

// One ConvLSTM timestep. CTA: 8x8 pixels (M=64) x N=256, 8 warps (2m x 4n).
// Persistent halos; zero barriers in mainloop; B via distance-2 LDG ring.
// PDL: x-halo staging overlaps the previous step's epilogue; dependent
// state (g_hh/g_c) touched only after cudaGridDependencySynchronize().
template<bool FIRST>
__global__ __launch_bounds__(256, 2)
void step_mma(const float* __restrict__ x, const float* __restrict__ bias,
              int t, int hsel, float* __restrict__ out, int last)
{
    __shared__ __align__(16) char sm[SM_TOT];

    const int tid  = threadIdx.x;
    const int lane = tid & 31;
    const int w    = tid >> 5;
    const int warp_m = w & 1;
    const int warp_n = w >> 1;
    const int b  = blockIdx.z;
    const int y0 = blockIdx.y * 8;
    const int x0 = blockIdx.x * 8;

    // ---- stage x halo (fp32 -> fp16 inline; independent of prior step) ----
    {
        const float* xframe = x + (size_t)(b * T_ + t) * H_ * W_ * CIN;
        for (int j = tid; j < 400; j += 256) {        // 100 px * 4 chunks
            const int p = j >> 2, q = j & 3;
            const int gy = y0 + p / 10 - 1, gx = x0 + p % 10 - 1;
            uint4 hv = make_uint4(0u, 0u, 0u, 0u);
            if ((unsigned)gy < H_ && (unsigned)gx < W_) {
                const float4* sp = (const float4*)
                    (xframe + ((size_t)gy * W_ + gx) * CIN + q * 8);
                float4 v0 = sp[0], v1 = sp[1];
                __half2 hh[4];
                hh[0] = __floats2half2_rn(v0.x, v0.y);
                hh[1] = __floats2half2_rn(v0.z, v0.w);
                hh[2] = __floats2half2_rn(v1.x, v1.y);
                hh[3] = __floats2half2_rn(v1.z, v1.w);
                hv = *(const uint4*)hh;
            }
            *(uint4*)(sm + SM_XH + p * XH_PITCH + q * 16) = hv;
        }
    }

    // wait for the previous kernel (prior step's epilogue / prep_bf)
    cudaGridDependencySynchronize();

    // ---- stage h halo ----
    if (!FIRST) {
        const __half* hframe = g_hh[hsel] + (size_t)b * H_ * W_ * F_;
        for (int j = tid; j < 800; j += 256) {        // 100 px * 8 chunks
            const int p = j >> 3, q = j & 7;
            const int gy = y0 + p / 10 - 1, gx = x0 + p % 10 - 1;
            uint4 v = make_uint4(0u, 0u, 0u, 0u);
            if ((unsigned)gy < H_ && (unsigned)gx < W_)
                v = *(const uint4*)(hframe + ((size_t)gy * W_ + gx) * F_ + q * 8);
            *(uint4*)(sm + SM_HH + p * HH_PITCH + q * 16) = v;
        }
    }
    __syncthreads();   // the only barrier before the epilogue

    // ---- per-lane A ldmatrix base addresses ----
    const uint32_t sb = smem_u32(sm);
    const int hi  = (lane >> 4) << 4;
    const int m0  = warp_m * 32 + (lane & 15);
    const int m1  = m0 + 16;
    const int f0p = (m0 >> 3) * 10 + (m0 & 7);
    const int f1p = (m1 >> 3) * 10 + (m1 & 7);
    const uint32_t aAx0 = sb + SM_XH + f0p * XH_PITCH + hi;
    const uint32_t aAx1 = sb + SM_XH + f1p * XH_PITCH + hi;
    const uint32_t aAh0 = sb + SM_HH + f0p * HH_PITCH + hi;
    const uint32_t aAh1 = sb + SM_HH + f1p * HH_PITCH + hi;

    float d[2][8][4];
    #pragma unroll
    for (int mt = 0; mt < 2; ++mt)
        #pragma unroll
        for (int nt = 0; nt < 8; ++nt)
            #pragma unroll
            for (int c = 0; c < 4; ++c) d[mt][nt][c] = 0.f;

    const int NS = FIRST ? 9 : NSL;
    // B fragment pointers (uint4 units; group idx stride = 32 uint4 = 512B)
    const uint4* bp = &g_bf[0][warp_n][0][lane];
    uint4 bb[4];
    bb[0] = bp[0];
    bb[1] = bp[32];

    #define SLICE_BODY(A0, A1, SOFF)                                          \
    do {                                                                      \
        const uint4* bnp = bp + ((s + 1 < NS) ? (4 * 8 * 32) : 0);            \
        _Pragma("unroll")                                                     \
        for (int kk = 0; kk < 2; ++kk) {                                      \
            uint32_t a0r[4], a1r[4];                                          \
            LDSM4(a0r[0], a0r[1], a0r[2], a0r[3], (A0) + (SOFF) + kk * 32);   \
            LDSM4(a1r[0], a1r[1], a1r[2], a1r[3], (A1) + (SOFF) + kk * 32);   \
            _Pragma("unroll")                                                 \
            for (int p = 0; p < 4; ++p) {                                     \
                const int idx = kk * 4 + p;                                   \
                const uint4* pf = (idx + 2 < 8) ? (bp + (idx + 2) * 32)       \
                                                : (bnp + (idx - 6) * 32);     \
                uint4 nb = *pf;                                               \
                uint4 cb = bb[p];                                             \
                MMA16816(d[0][2 * p + 0], a0r[0], a0r[1], a0r[2], a0r[3], cb.x, cb.y); \
                MMA16816(d[0][2 * p + 1], a0r[0], a0r[1], a0r[2], a0r[3], cb.z, cb.w); \
                MMA16816(d[1][2 * p + 0], a1r[0], a1r[1], a1r[2], a1r[3], cb.x, cb.y); \
                MMA16816(d[1][2 * p + 1], a1r[0], a1r[1], a1r[2], a1r[3], cb.z, cb.w); \
                bb[(p + 2) & 3] = nb;                                         \
            }                                                                 \
        }                                                                     \
        bp = bnp;                                                             \
    } while (0)

    // x-conv slices
    for (int s = 0; s < 9; ++s) {
        const int ky = s / 3, kx = s - 3 * (s / 3);
        const uint32_t soff = (uint32_t)(ky * 10 + kx) * XH_PITCH;
        SLICE_BODY(aAx0, aAx1, soff);
    }
    // h-conv slices
    if (!FIRST) {
        for (int s = 9; s < NSL; ++s) {
            const int u = s - 9, k9 = u >> 1, c0 = (u & 1) * 32;
            const int ky = k9 / 3, kx = k9 - 3 * (k9 / 3);
            const uint32_t soff = (uint32_t)(ky * 10 + kx) * HH_PITCH + c0 * 2;
            SLICE_BODY(aAh0, aAh1, soff);
        }
    }
    #undef SLICE_BODY

    // let the next step launch and stage its x-halo during our epilogue
    cudaTriggerProgrammaticLaunchCompletion();

    // ================= fused LSTM epilogue (verified layout) ==============
    __half* hhout = g_hh[hsel ^ 1];
    const int fq = 2 * (lane & 3);

    #pragma unroll
    for (int mt = 0; mt < 2; ++mt) {
        #pragma unroll
        for (int rh = 0; rh < 2; ++rh) {
            const int m  = warp_m * 32 + mt * 16 + rh * 8 + (lane >> 2);
            const int py = m >> 3, px = m & 7;
            const size_t pix =
                (((size_t)b * H_ + (y0 + py)) * W_ + (x0 + px)) * F_;
            #pragma unroll
            for (int t1 = 0; t1 < 2; ++t1) {
                const int f0 = warp_n * 16 + t1 * 8 + fq;
                float zi0 = d[mt][0 + t1][rh * 2 + 0], zi1 = d[mt][0 + t1][rh * 2 + 1];
                float zf0 = d[mt][2 + t1][rh * 2 + 0], zf1 = d[mt][2 + t1][rh * 2 + 1];
                float zc0 = d[mt][4 + t1][rh * 2 + 0], zc1 = d[mt][4 + t1][rh * 2 + 1];
                float zo0 = d[mt][6 + t1][rh * 2 + 0], zo1 = d[mt][6 + t1][rh * 2 + 1];

                float2 co = make_float2(0.f, 0.f);
                if (!FIRST) co = *(const float2*)&g_c[pix + f0];

                float ig0 = hsig(zi0 + bias[f0]);
                float fg0 = hsig(zf0 + bias[64 + f0]);
                float zz0 =      zc0 + bias[128 + f0];
                float og0 = hsig(zo0 + bias[192 + f0]);
                float cn0 = fg0 * co.x + ig0 * fmaxf(zz0, 0.f);
                float hn0 = og0 * fmaxf(cn0, 0.f);

                float ig1 = hsig(zi1 + bias[f0 + 1]);
                float fg1 = hsig(zf1 + bias[65 + f0]);
                float zz1 =      zc1 + bias[129 + f0];
                float og1 = hsig(zo1 + bias[193 + f0]);
                float cn1 = fg1 * co.y + ig1 * fmaxf(zz1, 0.f);
                float hn1 = og1 * fmaxf(cn1, 0.f);

                if (!last) {
                    *(float2*)&g_c[pix + f0] = make_float2(cn0, cn1);
                    *(__half2*)&hhout[pix + f0] = __floats2half2_rn(hn0, hn1);
                } else {
                    *(float2*)&out[pix + f0] = make_float2(hn0, hn1);
                }
            }
        }
    }
}

extern "C" void kernel_launch(void* const* d_in, const int* in_sizes, int n_in,
                              void* d_out, int out_size)
{
    const float* x = nullptr; const float* Wt = nullptr;
    const float* Ut = nullptr; const float* bias = nullptr;
    for (int i = 0; i < n_in; ++i) {
        switch (in_sizes[i]) {
            case B_*T_*H_*W_*CIN: x    = (const float*)d_in[i]; break;
            case 3*3*CIN*NC:      Wt   = (const float*)d_in[i]; break;
            case 3*3*F_*NC:       Ut   = (const float*)d_in[i]; break;
            case NC:              bias = (const float*)d_in[i]; break;
        }
    }
    if (!x || !Wt || !Ut || !bias) {
        x = (const float*)d_in[0]; Wt = (const float*)d_in[1];
        Ut = (const float*)d_in[2]; bias = (const float*)d_in[3];
    }
    float* out = (float*)d_out;

    prep_bf<<<dim3(NSL, 4), 256>>>(Wt, Ut);

    // PDL launch config: overlap each step with the tail of its predecessor
    cudaLaunchAttribute attrs[1];
    attrs[0].id = cudaLaunchAttributeProgrammaticStreamSerialization;
    attrs[0].val.programmaticStreamSerializationAllowed = 1;

    cudaLaunchConfig_t cfg = {};
    cfg.gridDim  = dim3(W_ / 8, H_ / 8, B_);   // 512 CTAs
    cfg.blockDim = dim3(256);
    cfg.dynamicSmemBytes = 0;
    cfg.stream = 0;
    cfg.attrs = attrs;
    cfg.numAttrs = 1;

    cudaLaunchKernelEx(&cfg, step_mma<true>, x, bias, 0, 0, out, 0);
    for (int t = 1; t < T_; ++t) {
        int last = (t == T_ - 1);
        cudaLaunchKernelEx(&cfg, step_mma<false>, x, bias, t, t & 1, out, last);
    }
}

// round 16
// speedup vs baseline: 1.8195x; 1.0327x over previous
#include <cuda_runtime.h>
#include <cuda_fp16.h>
#include <cstdint>

#define B_   8
#define T_   16
#define H_   64
#define W_   64
#define CIN  32
#define F_   64
#define NC   256          // 4*F gates [i,f,c,o]
#define NSL  27           // 9 x-slices + 18 h-slices (K=32 each)

// Persistent state. h in fp16 (feeds fp16 MMA), c in fp32.
__device__ __half g_hh[2][B_ * H_ * W_ * F_];
__device__ float  g_c[B_ * H_ * W_ * F_];
// Weights pre-packed in MMA B-fragment order (verified R5/R7):
// [slice][warp_n][idx = kk*4+p][lane] -> uint4
__device__ uint4 g_bf[NSL][4][8][32];

#define XH_PITCH 80     // bytes per halo pixel row (x: 64B data + pad)
#define HH_PITCH 144    // bytes per halo pixel row (h: 128B data + pad)
#define SM_XH 0
#define SM_HH 8000      // 100*80
#define SM_TOT (8000 + 100 * 144)   // 22400 B

__device__ __forceinline__ float hsig(float x) {
    return __saturatef((x + 3.0f) * 0.16666667f);  // hard_sigmoid
}
__device__ __forceinline__ uint32_t smem_u32(const void* p) {
    uint32_t a;
    asm("{ .reg .u64 t; cvta.to.shared.u64 t, %1; cvt.u32.u64 %0, t; }"
        : "=r"(a) : "l"(p));
    return a;
}

#define LDSM4(r0, r1, r2, r3, addr) \
    asm volatile("ldmatrix.sync.aligned.m8n8.x4.shared.b16 {%0,%1,%2,%3}, [%4];" \
        : "=r"(r0), "=r"(r1), "=r"(r2), "=r"(r3) : "r"(addr))

#define MMA16816(d, a0, a1, a2, a3, b0, b1) \
    asm volatile("mma.sync.aligned.m16n8k16.row.col.f32.f16.f16.f32 " \
        "{%0,%1,%2,%3}, {%4,%5,%6,%7}, {%8,%9}, {%0,%1,%2,%3};" \
        : "+f"((d)[0]), "+f"((d)[1]), "+f"((d)[2]), "+f"((d)[3]) \
        : "r"(a0), "r"(a1), "r"(a2), "r"(a3), "r"(b0), "r"(b1))

// ---- one-time prep: pack weights into B-fragment order (verified R5/R7) ----
__global__ void prep_bf(const float* __restrict__ Wt,
                        const float* __restrict__ Ut) {
    const int s    = blockIdx.x;          // 0..26
    const int wn   = blockIdx.y;          // 0..3
    const int idx  = threadIdx.x >> 5;    // 0..7
    const int lane = threadIdx.x & 31;
    const int kk = idx >> 2, p = idx & 3;

    uint32_t r[4];
    #pragma unroll
    for (int jm = 0; jm < 4; ++jm) {
        const int a  = 8 * jm + (lane >> 2);
        const int n  = wn * 64 + p * 16 + ((a >> 4) << 3) + (a & 7);
        const int jcol = ((n >> 4) & 3) * 64 + (n >> 6) * 16 + (n & 15);
        const int kb = kk * 16 + ((a >> 3) & 1) * 8 + 2 * (lane & 3);
        float w0, w1;
        if (s < 9) {
            const float* bp = Wt + ((size_t)s * CIN + kb) * NC + jcol;
            w0 = bp[0]; w1 = bp[NC];
        } else {
            const int u = s - 9, k9 = u >> 1, c0 = (u & 1) * 32;
            const float* bp = Ut + ((size_t)k9 * F_ + c0 + kb) * NC + jcol;
            w0 = bp[0]; w1 = bp[NC];
        }
        __half2 h2 = __floats2half2_rn(w0, w1);
        r[jm] = *(uint32_t*)&h2;
    }
    g_bf[s][wn][idx][lane] = make_uint4(r[0], r[1], r[2], r[3]);
}

// One ConvLSTM timestep. CTA: 8x8 pixels (M=64) x N=256, 8 warps (2m x 4n).
// PDL pipelining: x-halo staging AND the 9 x-conv slices run BEFORE
// cudaGridDependencySynchronize() (they depend only on x and g_bf, both
// final >= 2 kernels back for t >= 1); h-dependent work runs after.
template<bool FIRST>
__global__ __launch_bounds__(256, 2)
void step_mma(const float* __restrict__ x, const float* __restrict__ bias,
              int t, int hsel, float* __restrict__ out, int last)
{
    __shared__ __align__(16) char sm[SM_TOT];

    const int tid  = threadIdx.x;
    const int lane = tid & 31;
    const int w    = tid >> 5;
    const int warp_m = w & 1;
    const int warp_n = w >> 1;
    const int b  = blockIdx.z;
    const int y0 = blockIdx.y * 8;
    const int x0 = blockIdx.x * 8;

    // FIRST races prep_bf otherwise: sync before touching g_bf at all.
    if (FIRST) cudaGridDependencySynchronize();

    // ---- stage x halo (fp32 -> fp16 inline) ----
    {
        const float* xframe = x + (size_t)(b * T_ + t) * H_ * W_ * CIN;
        for (int j = tid; j < 400; j += 256) {        // 100 px * 4 chunks
            const int p = j >> 2, q = j & 3;
            const int gy = y0 + p / 10 - 1, gx = x0 + p % 10 - 1;
            uint4 hv = make_uint4(0u, 0u, 0u, 0u);
            if ((unsigned)gy < H_ && (unsigned)gx < W_) {
                const float4* sp = (const float4*)
                    (xframe + ((size_t)gy * W_ + gx) * CIN + q * 8);
                float4 v0 = sp[0], v1 = sp[1];
                __half2 hh[4];
                hh[0] = __floats2half2_rn(v0.x, v0.y);
                hh[1] = __floats2half2_rn(v0.z, v0.w);
                hh[2] = __floats2half2_rn(v1.x, v1.y);
                hh[3] = __floats2half2_rn(v1.z, v1.w);
                hv = *(const uint4*)hh;
            }
            *(uint4*)(sm + SM_XH + p * XH_PITCH + q * 16) = hv;
        }
    }
    __syncthreads();   // x halo ready

    // ---- per-lane A ldmatrix base addresses ----
    const uint32_t sb = smem_u32(sm);
    const int hi  = (lane >> 4) << 4;
    const int m0  = warp_m * 32 + (lane & 15);
    const int m1  = m0 + 16;
    const int f0p = (m0 >> 3) * 10 + (m0 & 7);
    const int f1p = (m1 >> 3) * 10 + (m1 & 7);
    const uint32_t aAx0 = sb + SM_XH + f0p * XH_PITCH + hi;
    const uint32_t aAx1 = sb + SM_XH + f1p * XH_PITCH + hi;
    const uint32_t aAh0 = sb + SM_HH + f0p * HH_PITCH + hi;
    const uint32_t aAh1 = sb + SM_HH + f1p * HH_PITCH + hi;

    float d[2][8][4];
    #pragma unroll
    for (int mt = 0; mt < 2; ++mt)
        #pragma unroll
        for (int nt = 0; nt < 8; ++nt)
            #pragma unroll
            for (int c = 0; c < 4; ++c) d[mt][nt][c] = 0.f;

    const int NS = FIRST ? 9 : NSL;
    // B fragment pointers (uint4 units; group idx stride = 32 uint4 = 512B)
    const uint4* bp = &g_bf[0][warp_n][0][lane];
    uint4 bb[4];
    bb[0] = bp[0];
    bb[1] = bp[32];

    #define SLICE_BODY(A0, A1, SOFF)                                          \
    do {                                                                      \
        const uint4* bnp = bp + ((s + 1 < NS) ? (4 * 8 * 32) : 0);            \
        _Pragma("unroll")                                                     \
        for (int kk = 0; kk < 2; ++kk) {                                      \
            uint32_t a0r[4], a1r[4];                                          \
            LDSM4(a0r[0], a0r[1], a0r[2], a0r[3], (A0) + (SOFF) + kk * 32);   \
            LDSM4(a1r[0], a1r[1], a1r[2], a1r[3], (A1) + (SOFF) + kk * 32);   \
            _Pragma("unroll")                                                 \
            for (int p = 0; p < 4; ++p) {                                     \
                const int idx = kk * 4 + p;                                   \
                const uint4* pf = (idx + 2 < 8) ? (bp + (idx + 2) * 32)       \
                                                : (bnp + (idx - 6) * 32);     \
                uint4 nb = *pf;                                               \
                uint4 cb = bb[p];                                             \
                MMA16816(d[0][2 * p + 0], a0r[0], a0r[1], a0r[2], a0r[3], cb.x, cb.y); \
                MMA16816(d[0][2 * p + 1], a0r[0], a0r[1], a0r[2], a0r[3], cb.z, cb.w); \
                MMA16816(d[1][2 * p + 0], a1r[0], a1r[1], a1r[2], a1r[3], cb.x, cb.y); \
                MMA16816(d[1][2 * p + 1], a1r[0], a1r[1], a1r[2], a1r[3], cb.z, cb.w); \
                bb[(p + 2) & 3] = nb;                                         \
            }                                                                 \
        }                                                                     \
        bp = bnp;                                                             \
    } while (0)

    // ---- 9 x-conv slices (pre-sync for t >= 1: overlap predecessor tail) --
    for (int s = 0; s < 9; ++s) {
        const int ky = s / 3, kx = s - 3 * (s / 3);
        const uint32_t soff = (uint32_t)(ky * 10 + kx) * XH_PITCH;
        SLICE_BODY(aAx0, aAx1, soff);
    }

    // ---- h-dependent phase ----
    if (!FIRST) {
        cudaGridDependencySynchronize();   // prior step fully complete
        const __half* hframe = g_hh[hsel] + (size_t)b * H_ * W_ * F_;
        for (int j = tid; j < 800; j += 256) {        // 100 px * 8 chunks
            const int p = j >> 3, q = j & 7;
            const int gy = y0 + p / 10 - 1, gx = x0 + p % 10 - 1;
            uint4 v = make_uint4(0u, 0u, 0u, 0u);
            if ((unsigned)gy < H_ && (unsigned)gx < W_)
                v = *(const uint4*)(hframe + ((size_t)gy * W_ + gx) * F_ + q * 8);
            *(uint4*)(sm + SM_HH + p * HH_PITCH + q * 16) = v;
        }
        __syncthreads();   // h halo ready

        for (int s = 9; s < NSL; ++s) {
            const int u = s - 9, k9 = u >> 1, c0 = (u & 1) * 32;
            const int ky = k9 / 3, kx = k9 - 3 * (k9 / 3);
            const uint32_t soff = (uint32_t)(ky * 10 + kx) * HH_PITCH + c0 * 2;
            SLICE_BODY(aAh0, aAh1, soff);
        }
    }
    #undef SLICE_BODY

    // let the next step launch and run its pre-sync phase during our tail
    cudaTriggerProgrammaticLaunchCompletion();

    // ================= fused LSTM epilogue (verified layout) ==============
    __half* hhout = g_hh[hsel ^ 1];
    const int fq = 2 * (lane & 3);

    #pragma unroll
    for (int mt = 0; mt < 2; ++mt) {
        #pragma unroll
        for (int rh = 0; rh < 2; ++rh) {
            const int m  = warp_m * 32 + mt * 16 + rh * 8 + (lane >> 2);
            const int py = m >> 3, px = m & 7;
            const size_t pix =
                (((size_t)b * H_ + (y0 + py)) * W_ + (x0 + px)) * F_;
            #pragma unroll
            for (int t1 = 0; t1 < 2; ++t1) {
                const int f0 = warp_n * 16 + t1 * 8 + fq;
                float zi0 = d[mt][0 + t1][rh * 2 + 0], zi1 = d[mt][0 + t1][rh * 2 + 1];
                float zf0 = d[mt][2 + t1][rh * 2 + 0], zf1 = d[mt][2 + t1][rh * 2 + 1];
                float zc0 = d[mt][4 + t1][rh * 2 + 0], zc1 = d[mt][4 + t1][rh * 2 + 1];
                float zo0 = d[mt][6 + t1][rh * 2 + 0], zo1 = d[mt][6 + t1][rh * 2 + 1];

                float2 co = make_float2(0.f, 0.f);
                if (!FIRST) co = *(const float2*)&g_c[pix + f0];

                float ig0 = hsig(zi0 + bias[f0]);
                float fg0 = hsig(zf0 + bias[64 + f0]);
                float zz0 =      zc0 + bias[128 + f0];
                float og0 = hsig(zo0 + bias[192 + f0]);
                float cn0 = fg0 * co.x + ig0 * fmaxf(zz0, 0.f);
                float hn0 = og0 * fmaxf(cn0, 0.f);

                float ig1 = hsig(zi1 + bias[f0 + 1]);
                float fg1 = hsig(zf1 + bias[65 + f0]);
                float zz1 =      zc1 + bias[129 + f0];
                float og1 = hsig(zo1 + bias[193 + f0]);
                float cn1 = fg1 * co.y + ig1 * fmaxf(zz1, 0.f);
                float hn1 = og1 * fmaxf(cn1, 0.f);

                if (!last) {
                    *(float2*)&g_c[pix + f0] = make_float2(cn0, cn1);
                    *(__half2*)&hhout[pix + f0] = __floats2half2_rn(hn0, hn1);
                } else {
                    *(float2*)&out[pix + f0] = make_float2(hn0, hn1);
                }
            }
        }
    }
}

extern "C" void kernel_launch(void* const* d_in, const int* in_sizes, int n_in,
                              void* d_out, int out_size)
{
    const float* x = nullptr; const float* Wt = nullptr;
    const float* Ut = nullptr; const float* bias = nullptr;
    for (int i = 0; i < n_in; ++i) {
        switch (in_sizes[i]) {
            case B_*T_*H_*W_*CIN: x    = (const float*)d_in[i]; break;
            case 3*3*CIN*NC:      Wt   = (const float*)d_in[i]; break;
            case 3*3*F_*NC:       Ut   = (const float*)d_in[i]; break;
            case NC:              bias = (const float*)d_in[i]; break;
        }
    }
    if (!x || !Wt || !Ut || !bias) {
        x = (const float*)d_in[0]; Wt = (const float*)d_in[1];
        Ut = (const float*)d_in[2]; bias = (const float*)d_in[3];
    }
    float* out = (float*)d_out;

    prep_bf<<<dim3(NSL, 4), 256>>>(Wt, Ut);

    // PDL launch config: overlap each step with the tail of its predecessor
    cudaLaunchAttribute attrs[1];
    attrs[0].id = cudaLaunchAttributeProgrammaticStreamSerialization;
    attrs[0].val.programmaticStreamSerializationAllowed = 1;

    cudaLaunchConfig_t cfg = {};
    cfg.gridDim  = dim3(W_ / 8, H_ / 8, B_);   // 512 CTAs
    cfg.blockDim = dim3(256);
    cfg.dynamicSmemBytes = 0;
    cfg.stream = 0;
    cfg.attrs = attrs;
    cfg.numAttrs = 1;

    cudaLaunchKernelEx(&cfg, step_mma<true>, x, bias, 0, 0, out, 0);
    for (int t = 1; t < T_; ++t) {
        int last = (t == T_ - 1);
        cudaLaunchKernelEx(&cfg, step_mma<false>, x, bias, t, t & 1, out, last);
    }
}

// round 17
// speedup vs baseline: 1.9001x; 1.0443x over previous
#include <cuda_runtime.h>
#include <cuda_fp16.h>
#include <cstdint>

#define B_   8
#define T_   16
#define H_   64
#define W_   64
#define CIN  32
#define F_   64
#define NC   256          // 4*F gates [i,f,c,o]
#define NSL  27           // 9 x-slices + 18 h-slices (K=32 each)

// Persistent state. h in fp16 (feeds fp16 MMA), c in fp32.
__device__ __half g_hh[2][B_ * H_ * W_ * F_];
__device__ float  g_c[B_ * H_ * W_ * F_];
// Weights pre-packed in MMA B-fragment order (verified R5/R7):
// [slice][warp_n][idx = kk*4+p][lane] -> uint4
__device__ uint4 g_bf[NSL][4][8][32];

#define XH_PITCH 80     // bytes per halo pixel row (x: 64B data + pad)
#define HH_PITCH 144    // bytes per halo pixel row (h: 128B data + pad)
#define SM_XH 0
#define SM_HH 8000      // 100*80
#define SM_TOT (8000 + 100 * 144)   // 22400 B

__device__ __forceinline__ float hsig(float x) {
    return __saturatef((x + 3.0f) * 0.16666667f);  // hard_sigmoid
}
__device__ __forceinline__ uint32_t smem_u32(const void* p) {
    uint32_t a;
    asm("{ .reg .u64 t; cvta.to.shared.u64 t, %1; cvt.u32.u64 %0, t; }"
        : "=r"(a) : "l"(p));
    return a;
}

#define LDSM4(r0, r1, r2, r3, addr) \
    asm volatile("ldmatrix.sync.aligned.m8n8.x4.shared.b16 {%0,%1,%2,%3}, [%4];" \
        : "=r"(r0), "=r"(r1), "=r"(r2), "=r"(r3) : "r"(addr))

#define MMA16816(d, a0, a1, a2, a3, b0, b1) \
    asm volatile("mma.sync.aligned.m16n8k16.row.col.f32.f16.f16.f32 " \
        "{%0,%1,%2,%3}, {%4,%5,%6,%7}, {%8,%9}, {%0,%1,%2,%3};" \
        : "+f"((d)[0]), "+f"((d)[1]), "+f"((d)[2]), "+f"((d)[3]) \
        : "r"(a0), "r"(a1), "r"(a2), "r"(a3), "r"(b0), "r"(b1))

// ---- one-time prep: pack weights into B-fragment order (verified R5/R7) ----
__global__ void prep_bf(const float* __restrict__ Wt,
                        const float* __restrict__ Ut) {
    const int s    = blockIdx.x;          // 0..26
    const int wn   = blockIdx.y;          // 0..3
    const int idx  = threadIdx.x >> 5;    // 0..7
    const int lane = threadIdx.x & 31;
    const int kk = idx >> 2, p = idx & 3;

    uint32_t r[4];
    #pragma unroll
    for (int jm = 0; jm < 4; ++jm) {
        const int a  = 8 * jm + (lane >> 2);
        const int n  = wn * 64 + p * 16 + ((a >> 4) << 3) + (a & 7);
        const int jcol = ((n >> 4) & 3) * 64 + (n >> 6) * 16 + (n & 15);
        const int kb = kk * 16 + ((a >> 3) & 1) * 8 + 2 * (lane & 3);
        float w0, w1;
        if (s < 9) {
            const float* bp = Wt + ((size_t)s * CIN + kb) * NC + jcol;
            w0 = bp[0]; w1 = bp[NC];
        } else {
            const int u = s - 9, k9 = u >> 1, c0 = (u & 1) * 32;
            const float* bp = Ut + ((size_t)k9 * F_ + c0 + kb) * NC + jcol;
            w0 = bp[0]; w1 = bp[NC];
        }
        __half2 h2 = __floats2half2_rn(w0, w1);
        r[jm] = *(uint32_t*)&h2;
    }
    g_bf[s][wn][idx][lane] = make_uint4(r[0], r[1], r[2], r[3]);
}

// One ConvLSTM timestep. CTA: 8x8 pixels (M=64) x N=256, 8 warps (2m x 4n).
// PDL pipelining: trigger at kernel ENTRY (successor's pre-sync phase reads
// only x and g_bf, final before we start, for t >= 1) -> successor overlaps
// our entire execution. x-halo + 9 x-conv slices run pre-sync; h-dependent
// work (h halo, 18 h-slices, c/h epilogue) runs after gridDepSync.
template<bool FIRST>
__global__ __launch_bounds__(256, 2)
void step_mma(const float* __restrict__ x, const float* __restrict__ bias,
              int t, int hsel, float* __restrict__ out, int last)
{
    __shared__ __align__(16) char sm[SM_TOT];

    const int tid  = threadIdx.x;
    const int lane = tid & 31;
    const int w    = tid >> 5;
    const int warp_m = w & 1;
    const int warp_n = w >> 1;
    const int b  = blockIdx.z;
    const int y0 = blockIdx.y * 8;
    const int x0 = blockIdx.x * 8;

    if (FIRST) {
        // must not let t=1 launch until prep_bf is complete: sync, THEN trigger
        cudaGridDependencySynchronize();
        cudaTriggerProgrammaticLaunchCompletion();
    } else {
        // successor's pre-sync phase touches nothing we write: release now
        cudaTriggerProgrammaticLaunchCompletion();
    }

    // ---- stage x halo (fp32 -> fp16 inline) ----
    {
        const float* xframe = x + (size_t)(b * T_ + t) * H_ * W_ * CIN;
        for (int j = tid; j < 400; j += 256) {        // 100 px * 4 chunks
            const int p = j >> 2, q = j & 3;
            const int gy = y0 + p / 10 - 1, gx = x0 + p % 10 - 1;
            uint4 hv = make_uint4(0u, 0u, 0u, 0u);
            if ((unsigned)gy < H_ && (unsigned)gx < W_) {
                const float4* sp = (const float4*)
                    (xframe + ((size_t)gy * W_ + gx) * CIN + q * 8);
                float4 v0 = sp[0], v1 = sp[1];
                __half2 hh[4];
                hh[0] = __floats2half2_rn(v0.x, v0.y);
                hh[1] = __floats2half2_rn(v0.z, v0.w);
                hh[2] = __floats2half2_rn(v1.x, v1.y);
                hh[3] = __floats2half2_rn(v1.z, v1.w);
                hv = *(const uint4*)hh;
            }
            *(uint4*)(sm + SM_XH + p * XH_PITCH + q * 16) = hv;
        }
    }
    __syncthreads();   // x halo ready

    // ---- per-lane A ldmatrix base addresses ----
    const uint32_t sb = smem_u32(sm);
    const int hi  = (lane >> 4) << 4;
    const int m0  = warp_m * 32 + (lane & 15);
    const int m1  = m0 + 16;
    const int f0p = (m0 >> 3) * 10 + (m0 & 7);
    const int f1p = (m1 >> 3) * 10 + (m1 & 7);
    const uint32_t aAx0 = sb + SM_XH + f0p * XH_PITCH + hi;
    const uint32_t aAx1 = sb + SM_XH + f1p * XH_PITCH + hi;
    const uint32_t aAh0 = sb + SM_HH + f0p * HH_PITCH + hi;
    const uint32_t aAh1 = sb + SM_HH + f1p * HH_PITCH + hi;

    float d[2][8][4];
    #pragma unroll
    for (int mt = 0; mt < 2; ++mt)
        #pragma unroll
        for (int nt = 0; nt < 8; ++nt)
            #pragma unroll
            for (int c = 0; c < 4; ++c) d[mt][nt][c] = 0.f;

    const int NS = FIRST ? 9 : NSL;
    // B fragment pointers (uint4 units; group idx stride = 32 uint4 = 512B)
    const uint4* bp = &g_bf[0][warp_n][0][lane];
    uint4 bb[4];
    bb[0] = bp[0];
    bb[1] = bp[32];

    #define SLICE_BODY(A0, A1, SOFF)                                          \
    do {                                                                      \
        const uint4* bnp = bp + ((s + 1 < NS) ? (4 * 8 * 32) : 0);            \
        _Pragma("unroll")                                                     \
        for (int kk = 0; kk < 2; ++kk) {                                      \
            uint32_t a0r[4], a1r[4];                                          \
            LDSM4(a0r[0], a0r[1], a0r[2], a0r[3], (A0) + (SOFF) + kk * 32);   \
            LDSM4(a1r[0], a1r[1], a1r[2], a1r[3], (A1) + (SOFF) + kk * 32);   \
            _Pragma("unroll")                                                 \
            for (int p = 0; p < 4; ++p) {                                     \
                const int idx = kk * 4 + p;                                   \
                const uint4* pf = (idx + 2 < 8) ? (bp + (idx + 2) * 32)       \
                                                : (bnp + (idx - 6) * 32);     \
                uint4 nb = *pf;                                               \
                uint4 cb = bb[p];                                             \
                MMA16816(d[0][2 * p + 0], a0r[0], a0r[1], a0r[2], a0r[3], cb.x, cb.y); \
                MMA16816(d[0][2 * p + 1], a0r[0], a0r[1], a0r[2], a0r[3], cb.z, cb.w); \
                MMA16816(d[1][2 * p + 0], a1r[0], a1r[1], a1r[2], a1r[3], cb.x, cb.y); \
                MMA16816(d[1][2 * p + 1], a1r[0], a1r[1], a1r[2], a1r[3], cb.z, cb.w); \
                bb[(p + 2) & 3] = nb;                                         \
            }                                                                 \
        }                                                                     \
        bp = bnp;                                                             \
    } while (0)

    // ---- 9 x-conv slices (pre-sync for t >= 1: overlap predecessor) ----
    for (int s = 0; s < 9; ++s) {
        const int ky = s / 3, kx = s - 3 * (s / 3);
        const uint32_t soff = (uint32_t)(ky * 10 + kx) * XH_PITCH;
        SLICE_BODY(aAx0, aAx1, soff);
    }

    // ---- h-dependent phase ----
    if (!FIRST) {
        cudaGridDependencySynchronize();   // prior step fully complete
        const __half* hframe = g_hh[hsel] + (size_t)b * H_ * W_ * F_;
        for (int j = tid; j < 800; j += 256) {        // 100 px * 8 chunks
            const int p = j >> 3, q = j & 7;
            const int gy = y0 + p / 10 - 1, gx = x0 + p % 10 - 1;
            uint4 v = make_uint4(0u, 0u, 0u, 0u);
            if ((unsigned)gy < H_ && (unsigned)gx < W_)
                v = *(const uint4*)(hframe + ((size_t)gy * W_ + gx) * F_ + q * 8);
            *(uint4*)(sm + SM_HH + p * HH_PITCH + q * 16) = v;
        }
        __syncthreads();   // h halo ready

        for (int s = 9; s < NSL; ++s) {
            const int u = s - 9, k9 = u >> 1, c0 = (u & 1) * 32;
            const int ky = k9 / 3, kx = k9 - 3 * (k9 / 3);
            const uint32_t soff = (uint32_t)(ky * 10 + kx) * HH_PITCH + c0 * 2;
            SLICE_BODY(aAh0, aAh1, soff);
        }
    }
    #undef SLICE_BODY

    // ================= fused LSTM epilogue (verified layout) ==============
    __half* hhout = g_hh[hsel ^ 1];
    const int fq = 2 * (lane & 3);

    #pragma unroll
    for (int mt = 0; mt < 2; ++mt) {
        #pragma unroll
        for (int rh = 0; rh < 2; ++rh) {
            const int m  = warp_m * 32 + mt * 16 + rh * 8 + (lane >> 2);
            const int py = m >> 3, px = m & 7;
            const size_t pix =
                (((size_t)b * H_ + (y0 + py)) * W_ + (x0 + px)) * F_;
            #pragma unroll
            for (int t1 = 0; t1 < 2; ++t1) {
                const int f0 = warp_n * 16 + t1 * 8 + fq;
                float zi0 = d[mt][0 + t1][rh * 2 + 0], zi1 = d[mt][0 + t1][rh * 2 + 1];
                float zf0 = d[mt][2 + t1][rh * 2 + 0], zf1 = d[mt][2 + t1][rh * 2 + 1];
                float zc0 = d[mt][4 + t1][rh * 2 + 0], zc1 = d[mt][4 + t1][rh * 2 + 1];
                float zo0 = d[mt][6 + t1][rh * 2 + 0], zo1 = d[mt][6 + t1][rh * 2 + 1];

                float2 co = make_float2(0.f, 0.f);
                if (!FIRST) co = *(const float2*)&g_c[pix + f0];

                float ig0 = hsig(zi0 + bias[f0]);
                float fg0 = hsig(zf0 + bias[64 + f0]);
                float zz0 =      zc0 + bias[128 + f0];
                float og0 = hsig(zo0 + bias[192 + f0]);
                float cn0 = fg0 * co.x + ig0 * fmaxf(zz0, 0.f);
                float hn0 = og0 * fmaxf(cn0, 0.f);

                float ig1 = hsig(zi1 + bias[f0 + 1]);
                float fg1 = hsig(zf1 + bias[65 + f0]);
                float zz1 =      zc1 + bias[129 + f0];
                float og1 = hsig(zo1 + bias[193 + f0]);
                float cn1 = fg1 * co.y + ig1 * fmaxf(zz1, 0.f);
                float hn1 = og1 * fmaxf(cn1, 0.f);

                if (!last) {
                    *(float2*)&g_c[pix + f0] = make_float2(cn0, cn1);
                    *(__half2*)&hhout[pix + f0] = __floats2half2_rn(hn0, hn1);
                } else {
                    *(float2*)&out[pix + f0] = make_float2(hn0, hn1);
                }
            }
        }
    }
}

extern "C" void kernel_launch(void* const* d_in, const int* in_sizes, int n_in,
                              void* d_out, int out_size)
{
    const float* x = nullptr; const float* Wt = nullptr;
    const float* Ut = nullptr; const float* bias = nullptr;
    for (int i = 0; i < n_in; ++i) {
        switch (in_sizes[i]) {
            case B_*T_*H_*W_*CIN: x    = (const float*)d_in[i]; break;
            case 3*3*CIN*NC:      Wt   = (const float*)d_in[i]; break;
            case 3*3*F_*NC:       Ut   = (const float*)d_in[i]; break;
            case NC:              bias = (const float*)d_in[i]; break;
        }
    }
    if (!x || !Wt || !Ut || !bias) {
        x = (const float*)d_in[0]; Wt = (const float*)d_in[1];
        Ut = (const float*)d_in[2]; bias = (const float*)d_in[3];
    }
    float* out = (float*)d_out;

    prep_bf<<<dim3(NSL, 4), 256>>>(Wt, Ut);

    // PDL launch config: overlap each step with its predecessor
    cudaLaunchAttribute attrs[1];
    attrs[0].id = cudaLaunchAttributeProgrammaticStreamSerialization;
    attrs[0].val.programmaticStreamSerializationAllowed = 1;

    cudaLaunchConfig_t cfg = {};
    cfg.gridDim  = dim3(W_ / 8, H_ / 8, B_);   // 512 CTAs
    cfg.blockDim = dim3(256);
    cfg.dynamicSmemBytes = 0;
    cfg.stream = 0;
    cfg.attrs = attrs;
    cfg.numAttrs = 1;

    cudaLaunchKernelEx(&cfg, step_mma<true>, x, bias, 0, 0, out, 0);
    for (int t = 1; t < T_; ++t) {
        int last = (t == T_ - 1);
        cudaLaunchKernelEx(&cfg, step_mma<false>, x, bias, t, t & 1, out, last);
    }
}